// round 12
// baseline (speedup 1.0000x reference)
#include <cuda_runtime.h>
#include <math.h>

#define B_ROWS 262144
#define KC 8
#define DC 32
#define TILE_R 128
#define NTILES (B_ROWS / TILE_R)      // 2048
#define NB1 304                        // pass1 grid (2 CTAs/SM)
#define NJ 17                          // triangle offsets 0..16
#define ITEMS_PER_K (1 + 32 + NJ * 32) // 577
#define NITEMS (KC * ITEMS_PER_K)      // 4616
#define EB 512                         // energy grid (512 samples/block)
#define P1_SMEM_FLOATS (2 * 8192 + 2 * 1024)   // 18432 floats = 72 KB
#define RSPLIT 16                      // reduce stage-1 groups (304 = 16*19)
#define RROWS  19

typedef unsigned long long ull;

// ---- f32x2 packed helpers (FFMA2 path; per-lane IEEE fp32 fma) ----
__device__ __forceinline__ ull ffma2(ull a, ull b, ull c) {
    ull d; asm("fma.rn.f32x2 %0,%1,%2,%3;" : "=l"(d) : "l"(a), "l"(b), "l"(c)); return d;
}
__device__ __forceinline__ ull dup2(float x) {
    ull d; asm("mov.b64 %0,{%1,%1};" : "=l"(d) : "f"(x)); return d;
}
__device__ __forceinline__ ull pack2(float lo, float hi) {
    ull d; asm("mov.b64 %0,{%1,%2};" : "=l"(d) : "f"(lo), "f"(hi)); return d;
}
__device__ __forceinline__ float2 unpack2(ull v) {
    float lo, hi; asm("mov.b64 {%0,%1},%2;" : "=f"(lo), "=f"(hi) : "l"(v));
    return make_float2(lo, hi);
}

// ---- cp.async helpers ----
__device__ __forceinline__ void cp16(void* smem, const void* gmem) {
    unsigned sa = (unsigned)__cvta_generic_to_shared(smem);
    asm volatile("cp.async.cg.shared.global [%0],[%1],16;" :: "r"(sa), "l"(gmem));
}
#define CP_COMMIT asm volatile("cp.async.commit_group;")
#define CP_WAIT1  asm volatile("cp.async.wait_group 1;")
#define CP_WAIT0  asm volatile("cp.async.wait_group 0;")

// ---- scratch ----
__device__ float d_partial1[(size_t)NB1 * NITEMS];   // ~5.6 MB
__device__ float d_partial1b[RSPLIT * NITEMS];       // stage-1 partials
__device__ float d_moments[NITEMS];
__device__ float d_Z[KC * DC * DC];                  // L^-1, zeros above diag
__device__ float d_u[KC * DC];                       // Z^T (Z mu)
__device__ float d_ck[KC];                           // log phi - 0.5(logdet + D log2pi + c2)
__device__ float d_sing[1];
__device__ float d_partial2[EB * 2];

// ============================================================
// Pass 1: compact triangular moments (R10 FFMA2 version, unchanged)
// ============================================================
__global__ __launch_bounds__(256, 2) void pass1_kernel(
    const float* __restrict__ feats, const float* __restrict__ gam)
{
    extern __shared__ __align__(16) float smem[];    // 72 KB dynamic
    float* fsb[2] = { smem,         smem + 8192 };
    float* gsb[2] = { smem + 16384, smem + 16384 + 1024 };

    const int tid  = threadIdx.x;
    const int w    = tid >> 5;
    const int lane = tid & 31;
    const int q    = w >> 2;     // k-quad 0..1
    const int sub  = w & 3;      // row subset

    ull acc2[4][8];              // packed pairs j=(1,2),(3,4),...,(15,16)
#pragma unroll
    for (int m = 0; m < 4; m++)
#pragma unroll
        for (int jp = 0; jp < 8; jp++) acc2[m][jp] = 0ull;
    float accJ0[4] = {0.f, 0.f, 0.f, 0.f};
    float accG[4] = {0.f, 0.f, 0.f, 0.f};
    float accS1[4] = {0.f, 0.f, 0.f, 0.f};

    int t = blockIdx.x;
    int cur = 0;
    {   // stage first tile (dup written by cp.async)
        const float* fsrc = feats + (size_t)t * TILE_R * DC;
#pragma unroll
        for (int i = tid; i < 1024; i += 256) {
            int row = i >> 3, c = i & 7;
            const float* src = fsrc + i * 4;
            cp16(fsb[0] + row * 64 + c * 4, src);
            cp16(fsb[0] + row * 64 + 32 + c * 4, src);
        }
        cp16(gsb[0] + tid * 4, gam + (size_t)t * TILE_R * KC + tid * 4);
        CP_COMMIT;
    }

    while (t < NTILES) {
        int tn = t + NB1;
        if (tn < NTILES) {
            const float* fsrc = feats + (size_t)tn * TILE_R * DC;
#pragma unroll
            for (int i = tid; i < 1024; i += 256) {
                int row = i >> 3, c = i & 7;
                const float* src = fsrc + i * 4;
                cp16(fsb[cur ^ 1] + row * 64 + c * 4, src);
                cp16(fsb[cur ^ 1] + row * 64 + 32 + c * 4, src);
            }
            cp16(gsb[cur ^ 1] + tid * 4, gam + (size_t)tn * TILE_R * KC + tid * 4);
            CP_COMMIT;
            CP_WAIT1;
        } else {
            CP_WAIT0;
        }
        __syncthreads();

        const float* fs = fsb[cur];
        const float* gs = gsb[cur];

#pragma unroll 2
        for (int rr = 0; rr < 32; rr++) {
            int r = rr * 4 + sub;
            const float* frow = fs + r * 64;
            float4 gv = *(const float4*)(gs + r * KC + q * 4);    // broadcast LDS.128
            float fe = frow[lane];
            float t0 = gv.x * fe, t1 = gv.y * fe, t2 = gv.z * fe, t3 = gv.w * fe;
            accG[0] += gv.x; accG[1] += gv.y; accG[2] += gv.z; accG[3] += gv.w;
            accS1[0] += t0; accS1[1] += t1; accS1[2] += t2; accS1[3] += t3;
            accJ0[0] = fmaf(t0, fe, accJ0[0]);
            accJ0[1] = fmaf(t1, fe, accJ0[1]);
            accJ0[2] = fmaf(t2, fe, accJ0[2]);
            accJ0[3] = fmaf(t3, fe, accJ0[3]);
            ull td0 = dup2(t0), td1 = dup2(t1), td2 = dup2(t2), td3 = dup2(t3);
#pragma unroll
            for (int jp = 0; jp < 8; jp++) {
                float fa = frow[lane + 2 * jp + 1];   // affine, conflict-free
                float fb = frow[lane + 2 * jp + 2];
                ull fp2 = pack2(fa, fb);
                acc2[0][jp] = ffma2(td0, fp2, acc2[0][jp]);
                acc2[1][jp] = ffma2(td1, fp2, acc2[1][jp]);
                acc2[2][jp] = ffma2(td2, fp2, acc2[2][jp]);
                acc2[3][jp] = ffma2(td3, fp2, acc2[3][jp]);
            }
        }
        __syncthreads();   // done reading buffer `cur` before it is restaged
        t = tn; cur ^= 1;
    }

    // ---- in-block combine: smem reused as red[8][577] ----
    for (int i = tid; i < NITEMS; i += 256) smem[i] = 0.f;
    __syncthreads();
    for (int s = 0; s < 4; s++) {
        if (sub == s) {
#pragma unroll
            for (int m = 0; m < 4; m++) {
                float* rk = smem + (4 * q + m) * ITEMS_PER_K;
                if (lane == 0) rk[0] += accG[m];
                rk[1 + lane] += accS1[m];
                rk[33 + lane] += accJ0[m];                       // j = 0
#pragma unroll
                for (int jp = 0; jp < 8; jp++) {
                    float2 v = unpack2(acc2[m][jp]);
                    rk[33 + (2 * jp + 1) * 32 + lane] += v.x;    // j = 2jp+1
                    rk[33 + (2 * jp + 2) * 32 + lane] += v.y;    // j = 2jp+2
                }
            }
        }
        __syncthreads();
    }
    for (int i = tid; i < NITEMS; i += 256)
        d_partial1[(size_t)blockIdx.x * NITEMS + i] = smem[i];
}

// ============================================================
// Reduce stage 1: 16 groups of 19 block-rows (deterministic fixed order)
// ============================================================
__global__ void reduce1a_kernel()
{
    int i = blockIdx.x * blockDim.x + threadIdx.x;
    if (i >= NITEMS) return;
    int g = blockIdx.y;
    const float* base = d_partial1 + (size_t)(g * RROWS) * NITEMS + i;
    float s = 0.f;
#pragma unroll
    for (int j = 0; j < RROWS; j++) s += base[(size_t)j * NITEMS];
    d_partial1b[g * NITEMS + i] = s;
}

// ============================================================
// Reduce stage 2: sum the 16 group partials (fixed order)
// ============================================================
__global__ void reduce1b_kernel()
{
    int i = blockIdx.x * blockDim.x + threadIdx.x;
    if (i >= NITEMS) return;
    float s = 0.f;
#pragma unroll
    for (int j = 0; j < RSPLIT; j++) s += d_partial1b[j * NITEMS + i];
    d_moments[i] = s;
}

// ============================================================
// Prep: sigma -> Cholesky -> Z=L^-1 ; t=Z mu, u=Z^T t, c2 folded into ck.
// ============================================================
__global__ __launch_bounds__(256) void prep_kernel()
{
    __shared__ __align__(16) float chol[KC][DC * 33];
    __shared__ float s1s[KC][DC];
    __shared__ float mus[KC][DC];
    __shared__ float ts[KC][DC];
    __shared__ float singp[KC];

    const int tid  = threadIdx.x;
    const int k    = tid >> 5;
    const int lane = tid & 31;

    const float* mom = d_moments + k * ITEMS_PER_K;
    const float gsum  = mom[0];
    const float denom = gsum + 1e-8f;
    const float s1    = mom[1 + lane];
    const float mu    = s1 / denom;
    s1s[k][lane] = s1;
    mus[k][lane] = mu;
    __syncwarp();

    float singAcc = 0.f;
#pragma unroll 1
    for (int d = 0; d < DC; d++) {
        int j = (d - lane) & 31;
        float s2;
        if (j <= 16) s2 = mom[33 + j * 32 + lane];
        else         s2 = mom[33 + ((lane - d) & 31) * 32 + d];
        float sig = (s2 - mus[k][d] * s1 - s1s[k][d] * mu + gsum * mus[k][d] * mu) / denom;
        if (d == lane) { sig += 1e-6f; singAcc = 1.f / (sig + 1e-8f); }
        chol[k][d * 33 + lane] = sig;
    }
#pragma unroll
    for (int o = 16; o; o >>= 1) singAcc += __shfl_xor_sync(0xffffffffu, singAcc, o);
    if (lane == 0) singp[k] = singAcc;

    const int i = lane;
    float myDiagLog = 0.f;
    for (int j = 0; j < DC; j++) {
        __syncwarp();
        float s = 0.f;
        if (i >= j) {
            s = chol[k][i * 33 + j];
            for (int m = 0; m < j; m++) s -= chol[k][i * 33 + m] * chol[k][j * 33 + m];
        }
        float sj  = __shfl_sync(0xffffffffu, s, j);
        float Ljj = sqrtf(sj);
        if (i == j) myDiagLog = logf(Ljj);
        if (i >= j) chol[k][i * 33 + j] = (i == j) ? Ljj : s / Ljj;
    }
    __syncwarp();

    float ld = myDiagLog;
#pragma unroll
    for (int o = 16; o; o >>= 1) ld += __shfl_xor_sync(0xffffffffu, ld, o);

    const int c = lane;
    float z[DC];
#pragma unroll
    for (int ii = 0; ii < DC; ii++) {
        float s = (ii == c) ? 1.f : 0.f;
#pragma unroll
        for (int j = 0; j < ii; j++) s -= chol[k][ii * 33 + j] * z[j];
        z[ii] = s / chol[k][ii * 33 + ii];
    }
    __syncwarp();
#pragma unroll
    for (int ii = 0; ii < DC; ii++) {
        chol[k][ii * 33 + c] = z[ii];
        d_Z[k * DC * DC + ii * DC + c] = z[ii];
    }
    __syncwarp();

    float tval = 0.f;
#pragma unroll
    for (int j = 0; j < DC; j++) tval = fmaf(chol[k][lane * 33 + j], mus[k][j], tval);
    ts[k][lane] = tval;
    __syncwarp();

    float c2 = tval * tval;
#pragma unroll
    for (int o = 16; o; o >>= 1) c2 += __shfl_xor_sync(0xffffffffu, c2, o);

    float uval = 0.f;
#pragma unroll
    for (int ii = 0; ii < DC; ii++) uval = fmaf(z[ii], ts[k][ii], uval);
    d_u[k * DC + c] = uval;

    if (lane == 0) {
        float phi = gsum / (float)B_ROWS;
        d_ck[k] = logf(phi + 1e-10f)
                - 0.5f * (2.f * ld + (float)DC * logf(6.28318f) + c2);
    }

    __syncthreads();
    if (tid == 0) {
        float s = 0.f;
        for (int kk = 0; kk < KC; kk++) s += singp[kk];
        d_sing[0] = s;
    }
}

// ============================================================
// Pass 3: energy.  2 samples/thread; f32x2 FFMA2 matvec with Z and u
// loaded as LDS.128 (two packed pairs per load; upper-triangle zeros
// keep over-read quads exact).
// ============================================================
__global__ __launch_bounds__(256, 2) void energy_kernel(
    const float* __restrict__ feats, const float* __restrict__ rec)
{
    __shared__ __align__(16) float Zs[KC * DC * DC];   // 32 KB
    __shared__ __align__(16) float us[KC * DC];
    __shared__ float cks[KC];
    __shared__ float red[256];

    const int tid = threadIdx.x;
    for (int i = tid; i < KC * DC * DC; i += 256) Zs[i] = d_Z[i];
    if (tid < KC * DC) us[tid] = d_u[tid];
    if (tid < KC)      cks[tid] = d_ck[tid];
    __syncthreads();

    const int b0 = blockIdx.x * 512 + tid;
    const int b1 = b0 + 256;

    // packed features: F0[cp] = (f0[2cp], f0[2cp+1])
    ull F0[16], F1[16];
    {
        const float4* p0 = (const float4*)(feats + (size_t)b0 * DC);
        const float4* p1 = (const float4*)(feats + (size_t)b1 * DC);
#pragma unroll
        for (int i = 0; i < 8; i++) {
            float4 a = p0[i];
            F0[2 * i]     = pack2(a.x, a.y);
            F0[2 * i + 1] = pack2(a.z, a.w);
            float4 b = p1[i];
            F1[2 * i]     = pack2(b.x, b.y);
            F1[2 * i + 1] = pack2(b.z, b.w);
        }
    }

    float m0 = -INFINITY, ss0 = 0.f;
    float m1 = -INFINITY, ss1 = 0.f;

#pragma unroll 1
    for (int k = 0; k < KC; k++) {
        const ulonglong2* Zq = (const ulonglong2*)(Zs + k * DC * DC);  // 8 quads/row
        const ulonglong2* uq = (const ulonglong2*)(us + k * DC);

        // dot = <f, u>  (packed, LDS.128)
        ull da0 = 0ull, da1 = 0ull;
#pragma unroll
        for (int cq = 0; cq < 8; cq++) {
            ulonglong2 u2 = uq[cq];                // broadcast LDS.128
            da0 = ffma2(u2.x, F0[2 * cq],     da0);
            da0 = ffma2(u2.y, F0[2 * cq + 1], da0);
            da1 = ffma2(u2.x, F1[2 * cq],     da1);
            da1 = ffma2(u2.y, F1[2 * cq + 1], da1);
        }
        float2 dv0 = unpack2(da0), dv1 = unpack2(da1);
        float dot0 = dv0.x + dv0.y, dot1 = dv1.x + dv1.y;

        // ||Z f||^2 via triangular packed matvec (quad loads)
        float sv0 = 0.f, sv1 = 0.f;
#pragma unroll
        for (int i = 0; i < DC; i++) {
            const ulonglong2* zrow = Zq + i * 8;
            ull wa0 = 0ull, wa1 = 0ull;
#pragma unroll
            for (int cq = 0; cq <= (i >> 2); cq++) {
                ulonglong2 zv = zrow[cq];          // broadcast LDS.128 (2 pairs)
                wa0 = ffma2(zv.x, F0[2 * cq],     wa0);
                wa0 = ffma2(zv.y, F0[2 * cq + 1], wa0);
                wa1 = ffma2(zv.x, F1[2 * cq],     wa1);
                wa1 = ffma2(zv.y, F1[2 * cq + 1], wa1);
            }
            float2 wv0 = unpack2(wa0), wv1 = unpack2(wa1);
            float w0 = wv0.x + wv0.y;
            float w1 = wv1.x + wv1.y;
            sv0 = fmaf(w0, w0, sv0);
            sv1 = fmaf(w1, w1, sv1);
        }
        float wlp0 = cks[k] + dot0 - 0.5f * sv0;
        float wlp1 = cks[k] + dot1 - 0.5f * sv1;
        float n0 = fmaxf(m0, wlp0);
        ss0 = ss0 * __expf(m0 - n0) + __expf(wlp0 - n0);
        m0 = n0;
        float n1 = fmaxf(m1, wlp1);
        ss1 = ss1 * __expf(m1 - n1) + __expf(wlp1 - n1);
        m1 = n1;
    }

    float te0 = -(m0 + __logf(ss0 + 1e-10f));
    float te1 = -(m1 + __logf(ss1 + 1e-10f));
    if (!isfinite(te0)) te0 = 0.f;
    if (!isfinite(te1)) te1 = 0.f;
    float resum = rec[b0] + rec[b1];

    red[tid] = te0 + te1; __syncthreads();
    for (int s = 128; s; s >>= 1) { if (tid < s) red[tid] += red[tid + s]; __syncthreads(); }
    if (tid == 0) d_partial2[blockIdx.x * 2 + 0] = red[0];
    __syncthreads();
    red[tid] = resum; __syncthreads();
    for (int s = 128; s; s >>= 1) { if (tid < s) red[tid] += red[tid + s]; __syncthreads(); }
    if (tid == 0) d_partial2[blockIdx.x * 2 + 1] = red[0];
}

// ============================================================
// Final combine
// ============================================================
__global__ __launch_bounds__(256) void final_kernel(float* __restrict__ out)
{
    __shared__ float red[256];
    const int tid = threadIdx.x;
    float e = 0.f, r = 0.f;
    for (int i = tid; i < EB; i += 256) {
        e += d_partial2[i * 2 + 0];
        r += d_partial2[i * 2 + 1];
    }
    red[tid] = e; __syncthreads();
    for (int s = 128; s; s >>= 1) { if (tid < s) red[tid] += red[tid + s]; __syncthreads(); }
    float esum = red[0]; __syncthreads();
    red[tid] = r; __syncthreads();
    for (int s = 128; s; s >>= 1) { if (tid < s) red[tid] += red[tid + s]; __syncthreads(); }
    if (tid == 0) {
        float rsum = red[0];
        out[0] = rsum / (float)B_ROWS
               + 0.1f * (esum / (float)B_ROWS)
               + 0.005f * d_sing[0];
    }
}

// ============================================================
extern "C" void kernel_launch(void* const* d_in, const int* in_sizes, int n_in,
                              void* d_out, int out_size)
{
    const float* gamma = nullptr;
    const float* feats = nullptr;
    const float* rec   = nullptr;
    for (int i = 0; i < n_in; i++) {
        if      (in_sizes[i] == B_ROWS * KC) gamma = (const float*)d_in[i];
        else if (in_sizes[i] == B_ROWS * DC) feats = (const float*)d_in[i];
        else if (in_sizes[i] == B_ROWS)      rec   = (const float*)d_in[i];
    }
    cudaFuncSetAttribute(pass1_kernel, cudaFuncAttributeMaxDynamicSharedMemorySize,
                         P1_SMEM_FLOATS * (int)sizeof(float));
    pass1_kernel<<<NB1, 256, P1_SMEM_FLOATS * sizeof(float)>>>(feats, gamma);
    {
        dim3 g((NITEMS + 255) / 256, RSPLIT);
        reduce1a_kernel<<<g, 256>>>();
    }
    reduce1b_kernel<<<(NITEMS + 255) / 256, 256>>>();
    prep_kernel<<<1, 256>>>();
    energy_kernel<<<EB, 256>>>(feats, rec);
    final_kernel<<<1, 256>>>((float*)d_out);
}

// round 13
// speedup vs baseline: 1.0351x; 1.0351x over previous
#include <cuda_runtime.h>
#include <math.h>

#define B_ROWS 262144
#define KC 8
#define DC 32
#define TILE_R 128
#define NTILES (B_ROWS / TILE_R)      // 2048
#define NB1 304                        // pass1 grid (2 CTAs/SM)
#define NJ 17                          // triangle offsets 0..16
#define ITEMS_PER_K (1 + 32 + NJ * 32) // 577
#define NITEMS (KC * ITEMS_PER_K)      // 4616
#define EB 512                         // energy grid (512 samples/block)
#define P1_SMEM_FLOATS (2 * 8192 + 2 * 1024)   // 18432 floats = 72 KB
#define RSPLIT 16                      // reduce stage-1 groups (304 = 16*19)
#define RROWS  19

typedef unsigned long long ull;

// ---- f32x2 packed helpers (FFMA2 path; per-lane IEEE fp32 fma) ----
__device__ __forceinline__ ull ffma2(ull a, ull b, ull c) {
    ull d; asm("fma.rn.f32x2 %0,%1,%2,%3;" : "=l"(d) : "l"(a), "l"(b), "l"(c)); return d;
}
__device__ __forceinline__ ull dup2(float x) {
    ull d; asm("mov.b64 %0,{%1,%1};" : "=l"(d) : "f"(x)); return d;
}
__device__ __forceinline__ ull pack2(float lo, float hi) {
    ull d; asm("mov.b64 %0,{%1,%2};" : "=l"(d) : "f"(lo), "f"(hi)); return d;
}
__device__ __forceinline__ float2 unpack2(ull v) {
    float lo, hi; asm("mov.b64 {%0,%1},%2;" : "=f"(lo), "=f"(hi) : "l"(v));
    return make_float2(lo, hi);
}

// ---- cp.async helpers ----
__device__ __forceinline__ void cp16(void* smem, const void* gmem) {
    unsigned sa = (unsigned)__cvta_generic_to_shared(smem);
    asm volatile("cp.async.cg.shared.global [%0],[%1],16;" :: "r"(sa), "l"(gmem));
}
#define CP_COMMIT asm volatile("cp.async.commit_group;")
#define CP_WAIT1  asm volatile("cp.async.wait_group 1;")
#define CP_WAIT0  asm volatile("cp.async.wait_group 0;")

// ---- scratch ----
__device__ float d_partial1[(size_t)NB1 * NITEMS];   // ~5.6 MB
__device__ float d_partial1b[RSPLIT * NITEMS];       // stage-1 partials
__device__ float d_moments[NITEMS];
__device__ float d_Zt[KC * DC * DC];                 // Z^T: Zt[k][c][i] = Z[i][c]
__device__ float d_u[KC * DC];                       // Z^T (Z mu)
__device__ float d_ck[KC];                           // log phi - 0.5(logdet + D log2pi + c2)
__device__ float d_sing[1];
__device__ float d_partial2[EB * 2];

// ============================================================
// Pass 1: compact triangular moments (R10 FFMA2 version, unchanged)
// ============================================================
__global__ __launch_bounds__(256, 2) void pass1_kernel(
    const float* __restrict__ feats, const float* __restrict__ gam)
{
    extern __shared__ __align__(16) float smem[];    // 72 KB dynamic
    float* fsb[2] = { smem,         smem + 8192 };
    float* gsb[2] = { smem + 16384, smem + 16384 + 1024 };

    const int tid  = threadIdx.x;
    const int w    = tid >> 5;
    const int lane = tid & 31;
    const int q    = w >> 2;     // k-quad 0..1
    const int sub  = w & 3;      // row subset

    ull acc2[4][8];              // packed pairs j=(1,2),(3,4),...,(15,16)
#pragma unroll
    for (int m = 0; m < 4; m++)
#pragma unroll
        for (int jp = 0; jp < 8; jp++) acc2[m][jp] = 0ull;
    float accJ0[4] = {0.f, 0.f, 0.f, 0.f};
    float accG[4] = {0.f, 0.f, 0.f, 0.f};
    float accS1[4] = {0.f, 0.f, 0.f, 0.f};

    int t = blockIdx.x;
    int cur = 0;
    {   // stage first tile (dup written by cp.async)
        const float* fsrc = feats + (size_t)t * TILE_R * DC;
#pragma unroll
        for (int i = tid; i < 1024; i += 256) {
            int row = i >> 3, c = i & 7;
            const float* src = fsrc + i * 4;
            cp16(fsb[0] + row * 64 + c * 4, src);
            cp16(fsb[0] + row * 64 + 32 + c * 4, src);
        }
        cp16(gsb[0] + tid * 4, gam + (size_t)t * TILE_R * KC + tid * 4);
        CP_COMMIT;
    }

    while (t < NTILES) {
        int tn = t + NB1;
        if (tn < NTILES) {
            const float* fsrc = feats + (size_t)tn * TILE_R * DC;
#pragma unroll
            for (int i = tid; i < 1024; i += 256) {
                int row = i >> 3, c = i & 7;
                const float* src = fsrc + i * 4;
                cp16(fsb[cur ^ 1] + row * 64 + c * 4, src);
                cp16(fsb[cur ^ 1] + row * 64 + 32 + c * 4, src);
            }
            cp16(gsb[cur ^ 1] + tid * 4, gam + (size_t)tn * TILE_R * KC + tid * 4);
            CP_COMMIT;
            CP_WAIT1;
        } else {
            CP_WAIT0;
        }
        __syncthreads();

        const float* fs = fsb[cur];
        const float* gs = gsb[cur];

#pragma unroll 2
        for (int rr = 0; rr < 32; rr++) {
            int r = rr * 4 + sub;
            const float* frow = fs + r * 64;
            float4 gv = *(const float4*)(gs + r * KC + q * 4);    // broadcast LDS.128
            float fe = frow[lane];
            float t0 = gv.x * fe, t1 = gv.y * fe, t2 = gv.z * fe, t3 = gv.w * fe;
            accG[0] += gv.x; accG[1] += gv.y; accG[2] += gv.z; accG[3] += gv.w;
            accS1[0] += t0; accS1[1] += t1; accS1[2] += t2; accS1[3] += t3;
            accJ0[0] = fmaf(t0, fe, accJ0[0]);
            accJ0[1] = fmaf(t1, fe, accJ0[1]);
            accJ0[2] = fmaf(t2, fe, accJ0[2]);
            accJ0[3] = fmaf(t3, fe, accJ0[3]);
            ull td0 = dup2(t0), td1 = dup2(t1), td2 = dup2(t2), td3 = dup2(t3);
#pragma unroll
            for (int jp = 0; jp < 8; jp++) {
                float fa = frow[lane + 2 * jp + 1];   // affine, conflict-free
                float fb = frow[lane + 2 * jp + 2];
                ull fp2 = pack2(fa, fb);
                acc2[0][jp] = ffma2(td0, fp2, acc2[0][jp]);
                acc2[1][jp] = ffma2(td1, fp2, acc2[1][jp]);
                acc2[2][jp] = ffma2(td2, fp2, acc2[2][jp]);
                acc2[3][jp] = ffma2(td3, fp2, acc2[3][jp]);
            }
        }
        __syncthreads();   // done reading buffer `cur` before it is restaged
        t = tn; cur ^= 1;
    }

    // ---- in-block combine: smem reused as red[8][577] ----
    for (int i = tid; i < NITEMS; i += 256) smem[i] = 0.f;
    __syncthreads();
    for (int s = 0; s < 4; s++) {
        if (sub == s) {
#pragma unroll
            for (int m = 0; m < 4; m++) {
                float* rk = smem + (4 * q + m) * ITEMS_PER_K;
                if (lane == 0) rk[0] += accG[m];
                rk[1 + lane] += accS1[m];
                rk[33 + lane] += accJ0[m];                       // j = 0
#pragma unroll
                for (int jp = 0; jp < 8; jp++) {
                    float2 v = unpack2(acc2[m][jp]);
                    rk[33 + (2 * jp + 1) * 32 + lane] += v.x;    // j = 2jp+1
                    rk[33 + (2 * jp + 2) * 32 + lane] += v.y;    // j = 2jp+2
                }
            }
        }
        __syncthreads();
    }
    for (int i = tid; i < NITEMS; i += 256)
        d_partial1[(size_t)blockIdx.x * NITEMS + i] = smem[i];
}

// ============================================================
// Reduce stage 1: 16 groups of 19 block-rows (deterministic fixed order)
// ============================================================
__global__ void reduce1a_kernel()
{
    int i = blockIdx.x * blockDim.x + threadIdx.x;
    if (i >= NITEMS) return;
    int g = blockIdx.y;
    const float* base = d_partial1 + (size_t)(g * RROWS) * NITEMS + i;
    float s = 0.f;
#pragma unroll
    for (int j = 0; j < RROWS; j++) s += base[(size_t)j * NITEMS];
    d_partial1b[g * NITEMS + i] = s;
}

// ============================================================
// Reduce stage 2: sum the 16 group partials (fixed order)
// ============================================================
__global__ void reduce1b_kernel()
{
    int i = blockIdx.x * blockDim.x + threadIdx.x;
    if (i >= NITEMS) return;
    float s = 0.f;
#pragma unroll
    for (int j = 0; j < RSPLIT; j++) s += d_partial1b[j * NITEMS + i];
    d_moments[i] = s;
}

// ============================================================
// Prep: sigma -> Cholesky -> Z=L^-1 (stored TRANSPOSED) ; t=Z mu,
// u=Z^T t, c2 folded into ck.
// ============================================================
__global__ __launch_bounds__(256) void prep_kernel()
{
    __shared__ __align__(16) float chol[KC][DC * 33];
    __shared__ float s1s[KC][DC];
    __shared__ float mus[KC][DC];
    __shared__ float ts[KC][DC];
    __shared__ float singp[KC];

    const int tid  = threadIdx.x;
    const int k    = tid >> 5;
    const int lane = tid & 31;

    const float* mom = d_moments + k * ITEMS_PER_K;
    const float gsum  = mom[0];
    const float denom = gsum + 1e-8f;
    const float s1    = mom[1 + lane];
    const float mu    = s1 / denom;
    s1s[k][lane] = s1;
    mus[k][lane] = mu;
    __syncwarp();

    float singAcc = 0.f;
#pragma unroll 1
    for (int d = 0; d < DC; d++) {
        int j = (d - lane) & 31;
        float s2;
        if (j <= 16) s2 = mom[33 + j * 32 + lane];
        else         s2 = mom[33 + ((lane - d) & 31) * 32 + d];
        float sig = (s2 - mus[k][d] * s1 - s1s[k][d] * mu + gsum * mus[k][d] * mu) / denom;
        if (d == lane) { sig += 1e-6f; singAcc = 1.f / (sig + 1e-8f); }
        chol[k][d * 33 + lane] = sig;
    }
#pragma unroll
    for (int o = 16; o; o >>= 1) singAcc += __shfl_xor_sync(0xffffffffu, singAcc, o);
    if (lane == 0) singp[k] = singAcc;

    const int i = lane;
    float myDiagLog = 0.f;
    for (int j = 0; j < DC; j++) {
        __syncwarp();
        float s = 0.f;
        if (i >= j) {
            s = chol[k][i * 33 + j];
            for (int m = 0; m < j; m++) s -= chol[k][i * 33 + m] * chol[k][j * 33 + m];
        }
        float sj  = __shfl_sync(0xffffffffu, s, j);
        float Ljj = sqrtf(sj);
        if (i == j) myDiagLog = logf(Ljj);
        if (i >= j) chol[k][i * 33 + j] = (i == j) ? Ljj : s / Ljj;
    }
    __syncwarp();

    float ld = myDiagLog;
#pragma unroll
    for (int o = 16; o; o >>= 1) ld += __shfl_xor_sync(0xffffffffu, ld, o);

    // Z = L^-1, lane c owns column c;  z[ii] = Z[ii][c] = Zt[c][ii]
    const int c = lane;
    float z[DC];
#pragma unroll
    for (int ii = 0; ii < DC; ii++) {
        float s = (ii == c) ? 1.f : 0.f;
#pragma unroll
        for (int j = 0; j < ii; j++) s -= chol[k][ii * 33 + j] * z[j];
        z[ii] = s / chol[k][ii * 33 + ii];
    }
    __syncwarp();
    // keep Z in workspace (for t) and store Zt row c contiguously
#pragma unroll
    for (int ii = 0; ii < DC; ii++) {
        chol[k][ii * 33 + c] = z[ii];
        d_Zt[k * DC * DC + c * DC + ii] = z[ii];
    }
    __syncwarp();

    float tval = 0.f;
#pragma unroll
    for (int j = 0; j < DC; j++) tval = fmaf(chol[k][lane * 33 + j], mus[k][j], tval);
    ts[k][lane] = tval;
    __syncwarp();

    float c2 = tval * tval;
#pragma unroll
    for (int o = 16; o; o >>= 1) c2 += __shfl_xor_sync(0xffffffffu, c2, o);

    float uval = 0.f;
#pragma unroll
    for (int ii = 0; ii < DC; ii++) uval = fmaf(z[ii], ts[k][ii], uval);
    d_u[k * DC + c] = uval;

    if (lane == 0) {
        float phi = gsum / (float)B_ROWS;
        d_ck[k] = logf(phi + 1e-10f)
                - 0.5f * (2.f * ld + (float)DC * logf(6.28318f) + c2);
    }

    __syncthreads();
    if (tid == 0) {
        float s = 0.f;
        for (int kk = 0; kk < KC; kk++) s += singp[kk];
        d_sing[0] = s;
    }
}

// ============================================================
// Pass 3: energy.  2 samples/thread; COLUMN-major packed matvec:
// V[pair_i] += (Zt[c][2i],Zt[c][2i+1]) * dup2(f_c) -> 16 independent
// FFMA2 chains per sample.  i processed in two halves to bound regs.
// wlp = ck' + <f,u> - 0.5*||Z f||^2
// ============================================================
__global__ __launch_bounds__(256, 2) void energy_kernel(
    const float* __restrict__ feats, const float* __restrict__ rec)
{
    __shared__ __align__(16) float Zts[KC * DC * DC];   // 32 KB (Zt layout)
    __shared__ __align__(16) float us[KC * DC];
    __shared__ float cks[KC];
    __shared__ float red[256];

    const int tid = threadIdx.x;
    for (int i = tid; i < KC * DC * DC; i += 256) Zts[i] = d_Zt[i];
    if (tid < KC * DC) us[tid] = d_u[tid];
    if (tid < KC)      cks[tid] = d_ck[tid];
    __syncthreads();

    const int b0 = blockIdx.x * 512 + tid;
    const int b1 = b0 + 256;

    float f0[DC], f1[DC];
    {
        const float4* p0 = (const float4*)(feats + (size_t)b0 * DC);
        const float4* p1 = (const float4*)(feats + (size_t)b1 * DC);
#pragma unroll
        for (int i = 0; i < 8; i++) {
            float4 a = p0[i];
            f0[i * 4 + 0] = a.x; f0[i * 4 + 1] = a.y; f0[i * 4 + 2] = a.z; f0[i * 4 + 3] = a.w;
            float4 b = p1[i];
            f1[i * 4 + 0] = b.x; f1[i * 4 + 1] = b.y; f1[i * 4 + 2] = b.z; f1[i * 4 + 3] = b.w;
        }
    }

    float m0 = -INFINITY, ss0 = 0.f;
    float m1 = -INFINITY, ss1 = 0.f;

#pragma unroll 1
    for (int k = 0; k < KC; k++) {
        const ulonglong2* Zq = (const ulonglong2*)(Zts + k * DC * DC);  // 8 quads/row
        const float4* uk = (const float4*)(us + k * DC);

        float dot0 = 0.f, dot1 = 0.f;
#pragma unroll
        for (int qd = 0; qd < 8; qd++) {
            float4 u4 = uk[qd];                    // broadcast LDS.128
            dot0 = fmaf(u4.x, f0[4 * qd + 0], dot0);
            dot0 = fmaf(u4.y, f0[4 * qd + 1], dot0);
            dot0 = fmaf(u4.z, f0[4 * qd + 2], dot0);
            dot0 = fmaf(u4.w, f0[4 * qd + 3], dot0);
            dot1 = fmaf(u4.x, f1[4 * qd + 0], dot1);
            dot1 = fmaf(u4.y, f1[4 * qd + 1], dot1);
            dot1 = fmaf(u4.z, f1[4 * qd + 2], dot1);
            dot1 = fmaf(u4.w, f1[4 * qd + 3], dot1);
        }

        ull macc0 = 0ull, macc1 = 0ull;

        // ---- half A: i in [0,16)  (quads 0..3; Zt[c][i]=0 for i<c exact)
        {
            ull V0[8], V1[8];
#pragma unroll
            for (int p = 0; p < 8; p++) { V0[p] = 0ull; V1[p] = 0ull; }
#pragma unroll
            for (int c = 0; c < 16; c++) {
                ull zd0 = dup2(f0[c]);
                ull zd1 = dup2(f1[c]);
                const ulonglong2* zr = Zq + c * 8;
#pragma unroll
                for (int qq = (c >> 2); qq < 4; qq++) {
                    ulonglong2 zz = zr[qq];        // broadcast LDS.128
                    V0[2 * qq]     = ffma2(zz.x, zd0, V0[2 * qq]);
                    V0[2 * qq + 1] = ffma2(zz.y, zd0, V0[2 * qq + 1]);
                    V1[2 * qq]     = ffma2(zz.x, zd1, V1[2 * qq]);
                    V1[2 * qq + 1] = ffma2(zz.y, zd1, V1[2 * qq + 1]);
                }
            }
#pragma unroll
            for (int p = 0; p < 8; p++) {
                macc0 = ffma2(V0[p], V0[p], macc0);
                macc1 = ffma2(V1[p], V1[p], macc1);
            }
        }

        // ---- half B: i in [16,32)  (quads 4..7)
        {
            ull V0[8], V1[8];
#pragma unroll
            for (int p = 0; p < 8; p++) { V0[p] = 0ull; V1[p] = 0ull; }
#pragma unroll
            for (int c = 0; c < 32; c++) {
                ull zd0 = dup2(f0[c]);
                ull zd1 = dup2(f1[c]);
                const ulonglong2* zr = Zq + c * 8;
                const int qstart = (c >> 2) < 4 ? 4 : (c >> 2);
#pragma unroll
                for (int qq = qstart; qq < 8; qq++) {
                    ulonglong2 zz = zr[qq];        // broadcast LDS.128
                    V0[2 * (qq - 4)]     = ffma2(zz.x, zd0, V0[2 * (qq - 4)]);
                    V0[2 * (qq - 4) + 1] = ffma2(zz.y, zd0, V0[2 * (qq - 4) + 1]);
                    V1[2 * (qq - 4)]     = ffma2(zz.x, zd1, V1[2 * (qq - 4)]);
                    V1[2 * (qq - 4) + 1] = ffma2(zz.y, zd1, V1[2 * (qq - 4) + 1]);
                }
            }
#pragma unroll
            for (int p = 0; p < 8; p++) {
                macc0 = ffma2(V0[p], V0[p], macc0);
                macc1 = ffma2(V1[p], V1[p], macc1);
            }
        }

        float2 mm0 = unpack2(macc0), mm1 = unpack2(macc1);
        float wlp0 = cks[k] + dot0 - 0.5f * (mm0.x + mm0.y);
        float wlp1 = cks[k] + dot1 - 0.5f * (mm1.x + mm1.y);
        float n0 = fmaxf(m0, wlp0);
        ss0 = ss0 * __expf(m0 - n0) + __expf(wlp0 - n0);
        m0 = n0;
        float n1 = fmaxf(m1, wlp1);
        ss1 = ss1 * __expf(m1 - n1) + __expf(wlp1 - n1);
        m1 = n1;
    }

    float te0 = -(m0 + __logf(ss0 + 1e-10f));
    float te1 = -(m1 + __logf(ss1 + 1e-10f));
    if (!isfinite(te0)) te0 = 0.f;
    if (!isfinite(te1)) te1 = 0.f;
    float resum = rec[b0] + rec[b1];

    red[tid] = te0 + te1; __syncthreads();
    for (int s = 128; s; s >>= 1) { if (tid < s) red[tid] += red[tid + s]; __syncthreads(); }
    if (tid == 0) d_partial2[blockIdx.x * 2 + 0] = red[0];
    __syncthreads();
    red[tid] = resum; __syncthreads();
    for (int s = 128; s; s >>= 1) { if (tid < s) red[tid] += red[tid + s]; __syncthreads(); }
    if (tid == 0) d_partial2[blockIdx.x * 2 + 1] = red[0];
}

// ============================================================
// Final combine
// ============================================================
__global__ __launch_bounds__(256) void final_kernel(float* __restrict__ out)
{
    __shared__ float red[256];
    const int tid = threadIdx.x;
    float e = 0.f, r = 0.f;
    for (int i = tid; i < EB; i += 256) {
        e += d_partial2[i * 2 + 0];
        r += d_partial2[i * 2 + 1];
    }
    red[tid] = e; __syncthreads();
    for (int s = 128; s; s >>= 1) { if (tid < s) red[tid] += red[tid + s]; __syncthreads(); }
    float esum = red[0]; __syncthreads();
    red[tid] = r; __syncthreads();
    for (int s = 128; s; s >>= 1) { if (tid < s) red[tid] += red[tid + s]; __syncthreads(); }
    if (tid == 0) {
        float rsum = red[0];
        out[0] = rsum / (float)B_ROWS
               + 0.1f * (esum / (float)B_ROWS)
               + 0.005f * d_sing[0];
    }
}

// ============================================================
extern "C" void kernel_launch(void* const* d_in, const int* in_sizes, int n_in,
                              void* d_out, int out_size)
{
    const float* gamma = nullptr;
    const float* feats = nullptr;
    const float* rec   = nullptr;
    for (int i = 0; i < n_in; i++) {
        if      (in_sizes[i] == B_ROWS * KC) gamma = (const float*)d_in[i];
        else if (in_sizes[i] == B_ROWS * DC) feats = (const float*)d_in[i];
        else if (in_sizes[i] == B_ROWS)      rec   = (const float*)d_in[i];
    }
    cudaFuncSetAttribute(pass1_kernel, cudaFuncAttributeMaxDynamicSharedMemorySize,
                         P1_SMEM_FLOATS * (int)sizeof(float));
    pass1_kernel<<<NB1, 256, P1_SMEM_FLOATS * sizeof(float)>>>(feats, gamma);
    {
        dim3 g((NITEMS + 255) / 256, RSPLIT);
        reduce1a_kernel<<<g, 256>>>();
    }
    reduce1b_kernel<<<(NITEMS + 255) / 256, 256>>>();
    prep_kernel<<<1, 256>>>();
    energy_kernel<<<EB, 256>>>(feats, rec);
    final_kernel<<<1, 256>>>((float*)d_out);
}